// round 15
// baseline (speedup 1.0000x reference)
#include <cuda_runtime.h>
#include <cstdint>

#define N_NODES 100000
#define N_EDGES 3200000
#define D 16
#define TPB 256

// -------- allocation-free scratch (__device__ globals, ~26 MB) ------------
__device__ __align__(16) float g_xbufA[N_NODES * D];
__device__ __align__(16) float g_xbufB[N_NODES * D];
__device__ float g_invdeg[N_NODES];      // 1 / max(deg,1)
__device__ int   g_deg   [N_NODES];      // in-degree
__device__ int   g_off   [N_NODES + 1];  // CSR row offsets
__device__ int   g_cursor[N_NODES];      // fill cursors
__device__ int   g_esrc  [N_EDGES];      // CSR src indices (int32)
__device__ int   g_is64;                 // 1 if edge_index is int64, 0 if int32

__device__ __forceinline__ int clamp_node(int v) {
    v = v < 0 ? 0 : v;
    return v >= N_NODES ? N_NODES - 1 : v;
}

// Read edge-index element `elem` (flat element index into the int32/int64
// array), dtype chosen by g_is64. `w` = edge_index viewed as 32-bit words.
__device__ __forceinline__ int load_idx(const int* __restrict__ w, int is64, int elem) {
    // int64 little-endian: value's low word is at word 2*elem.
    return is64 ? w[2 * elem] : w[elem];
}

// ---------------------------------------------------------------------------
// Dtype detection: odd 32-bit words of the first 1024 elements are the high
// halves if int64 (all zero, since ids < 2^17); if int32 they are node ids
// (all-zero probability ~ (1e-5)^1024). One warp.
// ---------------------------------------------------------------------------
__global__ void detect_kernel(const int* __restrict__ w) {
    int lane = threadIdx.x;
    int acc = 0;
    for (int i = lane; i < 1024; i += 32) acc |= w[2 * i + 1];
#pragma unroll
    for (int m = 16; m >= 1; m >>= 1) acc |= __shfl_xor_sync(0xffffffffu, acc, m);
    if (lane == 0) g_is64 = (acc == 0) ? 1 : 0;
}

// ---------------------------------------------------------------------------
// Pass 0: zero degree + cursors
// ---------------------------------------------------------------------------
__global__ void zero_kernel() {
    int i = blockIdx.x * blockDim.x + threadIdx.x;
    if (i < N_NODES) { g_deg[i] = 0; g_cursor[i] = 0; }
}

// ---------------------------------------------------------------------------
// Pass 1: in-degree histogram (int atomics, clamped indices)
// ---------------------------------------------------------------------------
__global__ void deg_kernel(const int* __restrict__ w) {
    int e = blockIdx.x * blockDim.x + threadIdx.x;
    if (e >= N_EDGES) return;
    int d = clamp_node(load_idx(w, g_is64, N_EDGES + e));   // dst row
    atomicAdd(&g_deg[d], 1);
}

// ---------------------------------------------------------------------------
// Pass 2: exclusive prefix scan of deg -> g_off, plus invdeg. Single block.
// ---------------------------------------------------------------------------
__global__ void __launch_bounds__(1024)
scan_kernel() {
    __shared__ int warp_sums[32];
    __shared__ int s_carry;
    int tid  = threadIdx.x;
    int lane = tid & 31, wid = tid >> 5;
    if (tid == 0) s_carry = 0;
    __syncthreads();

    for (int base = 0; base < N_NODES; base += 1024) {
        int i = base + tid;
        int v = (i < N_NODES) ? g_deg[i] : 0;
        int xs = v;  // inclusive warp scan
#pragma unroll
        for (int ofs = 1; ofs < 32; ofs <<= 1) {
            int y = __shfl_up_sync(0xffffffffu, xs, ofs);
            if (lane >= ofs) xs += y;
        }
        if (lane == 31) warp_sums[wid] = xs;
        __syncthreads();
        if (wid == 0) {
            int ws = warp_sums[lane];
#pragma unroll
            for (int ofs = 1; ofs < 32; ofs <<= 1) {
                int y = __shfl_up_sync(0xffffffffu, ws, ofs);
                if (lane >= ofs) ws += y;
            }
            warp_sums[lane] = ws;
        }
        __syncthreads();
        int warp_prefix = (wid > 0) ? warp_sums[wid - 1] : 0;
        int incl = s_carry + warp_prefix + xs;
        if (i < N_NODES) {
            g_off[i + 1] = incl;
            g_invdeg[i]  = 1.0f / (float)(v > 1 ? v : 1);
        }
        __syncthreads();
        if (tid == 1023) s_carry = incl;
        __syncthreads();
    }
    if (tid == 0) g_off[0] = 0;
}

// ---------------------------------------------------------------------------
// Pass 3: CSR fill. Slot order within a node is atomic-arbitrary; it only
// permutes a ~32-term fp32 sum (ulp-level, far below 1e-3).
// ---------------------------------------------------------------------------
__global__ void fill_kernel(const int* __restrict__ w) {
    int e = blockIdx.x * blockDim.x + threadIdx.x;
    if (e >= N_EDGES) return;
    int is64 = g_is64;
    int s = clamp_node(load_idx(w, is64, e));             // src row
    int d = clamp_node(load_idx(w, is64, N_EDGES + e));   // dst row
    int pos = atomicAdd(&g_cursor[d], 1);
    g_esrc[g_off[d] + pos] = s;
}

// ---------------------------------------------------------------------------
// Fused per-layer kernel: warp per node.
//   agg[n] = mean over in-edges of x[src]       (pure gather, no atomics)
//   out[n] = Wl @ agg + (Wr+Wlin) @ x[n] + (bl+blin)
// 4 lanes per edge (one float4 quad each) -> 8 edges per warp iteration;
// shfl_xor folds the 8 edge slots. Lanes 0..15 then each compute one
// output dim from shared-staged agg/x rows.
// in_sel/out_sel: 0 = kernel parameter, 1 = g_xbufA, 2 = g_xbufB.
// 100000 nodes / 8 warps per block = 12500 blocks exactly.
// ---------------------------------------------------------------------------
__global__ void __launch_bounds__(TPB)
layer_kernel(const float* __restrict__ x_param, float* __restrict__ out_param,
             int in_sel, int out_sel,
             const float* __restrict__ Wl,   const float* __restrict__ bl,
             const float* __restrict__ Wr,   const float* __restrict__ Wlin,
             const float* __restrict__ blin) {
    __shared__ float sWl[D * D];        // row-major, row = output dim
    __shared__ float sWc[D * D];        // Wr + Wlin
    __shared__ float sb[D];             // bl + blin
    __shared__ float s_a[TPB / 32][D];  // per-warp aggregated row
    __shared__ float s_x[TPB / 32][D];  // per-warp x[n]

    const float* x   = (in_sel == 0) ? x_param
                     : (in_sel == 1) ? (const float*)g_xbufA : (const float*)g_xbufB;
    float*       out = (out_sel == 0) ? out_param
                     : (out_sel == 1) ? (float*)g_xbufA : (float*)g_xbufB;

    int tid = threadIdx.x;
    sWl[tid] = Wl[tid];
    sWc[tid] = Wr[tid] + Wlin[tid];
    if (tid < D) sb[tid] = bl[tid] + blin[tid];
    __syncthreads();

    int wid  = tid >> 5;
    int lane = tid & 31;
    int n    = blockIdx.x * (TPB / 32) + wid;

    int start = g_off[n];
    int end   = g_off[n + 1];
    int q     = lane & 3;    // float4 quad within the 16-float row
    int sub   = lane >> 2;   // edge slot 0..7

    float4 acc = make_float4(0.f, 0.f, 0.f, 0.f);
    for (int e = start + sub; e < end; e += 8) {
        int s = g_esrc[e];
        float4 v = *reinterpret_cast<const float4*>(x + (size_t)s * D + q * 4);
        acc.x += v.x; acc.y += v.y; acc.z += v.z; acc.w += v.w;
    }
#pragma unroll
    for (int m = 4; m <= 16; m <<= 1) {   // fold edge slots (same-q lanes)
        acc.x += __shfl_xor_sync(0xffffffffu, acc.x, m);
        acc.y += __shfl_xor_sync(0xffffffffu, acc.y, m);
        acc.z += __shfl_xor_sync(0xffffffffu, acc.z, m);
        acc.w += __shfl_xor_sync(0xffffffffu, acc.w, m);
    }

    float inv = g_invdeg[n];
    if (sub == 0) {                       // lanes 0..3: scaled agg quad
        s_a[wid][q * 4 + 0] = acc.x * inv;
        s_a[wid][q * 4 + 1] = acc.y * inv;
        s_a[wid][q * 4 + 2] = acc.z * inv;
        s_a[wid][q * 4 + 3] = acc.w * inv;
    } else if (sub == 1) {                // lanes 4..7: stage x[n]
        float4 xv = *reinterpret_cast<const float4*>(x + (size_t)n * D + q * 4);
        s_x[wid][q * 4 + 0] = xv.x;
        s_x[wid][q * 4 + 1] = xv.y;
        s_x[wid][q * 4 + 2] = xv.z;
        s_x[wid][q * 4 + 3] = xv.w;
    }
    __syncwarp(0xffffffffu);

    if (lane < D) {                       // one output dim per lane
        float o = sb[lane];
        const float* wl = sWl + lane * D;
        const float* wc = sWc + lane * D;
#pragma unroll
        for (int k = 0; k < D; k++)
            o += wl[k] * s_a[wid][k] + wc[k] * s_x[wid][k];
        out[(size_t)n * D + lane] = o;
    }
}

// ---------------------------------------------------------------------------
// Launch: kernel launches ONLY (no symbol queries, no memcpy, no allocs).
// ---------------------------------------------------------------------------
extern "C" void kernel_launch(void* const* d_in, const int* in_sizes, int n_in,
                              void* d_out, int out_size) {
    const float* x    = (const float*)d_in[0];
    const int*   eiw  = (const int*)d_in[1];   // edge_index as 32-bit words
    const float* Wl   = (const float*)d_in[2];
    const float* bl   = (const float*)d_in[3];
    const float* Wr   = (const float*)d_in[4];
    const float* Wlin = (const float*)d_in[5];
    const float* blin = (const float*)d_in[6];
    float*       out  = (float*)d_out;

    const int NODE_BLK  = (N_NODES + TPB - 1) / TPB;
    const int EDGE_BLK  = (N_EDGES + TPB - 1) / TPB;
    const int LAYER_BLK = N_NODES / (TPB / 32);      // 12500, exact

    // dtype detect + CSR build (degree is layer-invariant)
    detect_kernel<<<1, 32>>>(eiw);
    zero_kernel<<<NODE_BLK, TPB>>>();
    deg_kernel <<<EDGE_BLK, TPB>>>(eiw);
    scan_kernel<<<1, 1024>>>();
    fill_kernel<<<EDGE_BLK, TPB>>>(eiw);

    // 3 fused SAGE layers: x -> A -> B -> out (never in-place)
    layer_kernel<<<LAYER_BLK, TPB>>>(x,       nullptr, 0, 1,
        Wl + 0 * D * D, bl + 0 * D, Wr + 0 * D * D, Wlin + 0 * D * D, blin + 0 * D);
    layer_kernel<<<LAYER_BLK, TPB>>>(nullptr, nullptr, 1, 2,
        Wl + 1 * D * D, bl + 1 * D, Wr + 1 * D * D, Wlin + 1 * D * D, blin + 1 * D);
    layer_kernel<<<LAYER_BLK, TPB>>>(nullptr, out,     2, 0,
        Wl + 2 * D * D, bl + 2 * D, Wr + 2 * D * D, Wlin + 2 * D * D, blin + 2 * D);
}

// round 16
// speedup vs baseline: 1.2982x; 1.2982x over previous
#include <cuda_runtime.h>
#include <cstdint>

#define N_NODES 100000
#define N_EDGES 3200000
#define D 16
#define TPB 256

#define SCAN_CHUNK 1024
#define SCAN_BLOCKS ((N_NODES + SCAN_CHUNK - 1) / SCAN_CHUNK)   // 98

// -------- allocation-free scratch (__device__ globals, ~26 MB) ------------
__device__ __align__(16) float g_xbufA[N_NODES * D];
__device__ __align__(16) float g_xbufB[N_NODES * D];
__device__ float g_invdeg[N_NODES];        // 1 / max(deg,1)
__device__ int   g_deg   [N_NODES];        // in-degree
__device__ int   g_off   [N_NODES + 1];    // CSR row offsets
__device__ int   g_cursor[N_NODES];        // fill cursors
__device__ int   g_esrc  [N_EDGES];        // CSR src indices (int32)
__device__ int   g_partial[SCAN_BLOCKS];   // per-block sums
__device__ int   g_pscan [SCAN_BLOCKS];    // exclusive scan of partials
__device__ int   g_is64;                   // 1 if edge_index is int64

__device__ __forceinline__ int clamp_node(int v) {
    v = v < 0 ? 0 : v;
    return v >= N_NODES ? N_NODES - 1 : v;
}

// Edge-index element `elem` via 32-bit word view (handles int32 or int64 LE).
__device__ __forceinline__ int load_idx(const int* __restrict__ w, int is64, int elem) {
    return is64 ? w[2 * elem] : w[elem];
}

// ---------------------------------------------------------------------------
// Dtype detection: odd words of first 1024 elements are int64 high halves
// (all zero, ids < 2^17) or int32 payload (all-zero prob ~ (1e-5)^1024).
// ---------------------------------------------------------------------------
__global__ void detect_kernel(const int* __restrict__ w) {
    int lane = threadIdx.x;
    int acc = 0;
    for (int i = lane; i < 1024; i += 32) acc |= w[2 * i + 1];
#pragma unroll
    for (int m = 16; m >= 1; m >>= 1) acc |= __shfl_xor_sync(0xffffffffu, acc, m);
    if (lane == 0) g_is64 = (acc == 0) ? 1 : 0;
}

// ---------------------------------------------------------------------------
// Zero in-degree (cursors are zeroed inside scan pass C)
// ---------------------------------------------------------------------------
__global__ void zero_kernel() {
    int i = blockIdx.x * blockDim.x + threadIdx.x;
    if (i < N_NODES) g_deg[i] = 0;
}

// ---------------------------------------------------------------------------
// In-degree histogram
// ---------------------------------------------------------------------------
__global__ void deg_kernel(const int* __restrict__ w) {
    int e = blockIdx.x * blockDim.x + threadIdx.x;
    if (e >= N_EDGES) return;
    int d = clamp_node(load_idx(w, g_is64, N_EDGES + e));
    atomicAdd(&g_deg[d], 1);
}

// ---------------------------------------------------------------------------
// Grid-wide exclusive scan of g_deg, 3 passes.
// ---------------------------------------------------------------------------

// Block-wide inclusive scan of one value per thread (1024 threads).
__device__ __forceinline__ int block_incl_scan(int v, int tid) {
    __shared__ int warp_sums[32];
    int lane = tid & 31, wid = tid >> 5;
    int xs = v;
#pragma unroll
    for (int ofs = 1; ofs < 32; ofs <<= 1) {
        int y = __shfl_up_sync(0xffffffffu, xs, ofs);
        if (lane >= ofs) xs += y;
    }
    if (lane == 31) warp_sums[wid] = xs;
    __syncthreads();
    if (wid == 0) {
        int ws = warp_sums[lane];
#pragma unroll
        for (int ofs = 1; ofs < 32; ofs <<= 1) {
            int y = __shfl_up_sync(0xffffffffu, ws, ofs);
            if (lane >= ofs) ws += y;
        }
        warp_sums[lane] = ws;
    }
    __syncthreads();
    return xs + ((wid > 0) ? warp_sums[wid - 1] : 0);
}

// Pass A: per-block chunk sums.
__global__ void __launch_bounds__(SCAN_CHUNK)
scanA_kernel() {
    int tid = threadIdx.x;
    int i = blockIdx.x * SCAN_CHUNK + tid;
    int v = (i < N_NODES) ? g_deg[i] : 0;
#pragma unroll
    for (int m = 16; m >= 1; m >>= 1) v += __shfl_xor_sync(0xffffffffu, v, m);
    __shared__ int ws[32];
    if ((tid & 31) == 0) ws[tid >> 5] = v;
    __syncthreads();
    if (tid < 32) {
        int s = ws[tid];
#pragma unroll
        for (int m = 16; m >= 1; m >>= 1) s += __shfl_xor_sync(0xffffffffu, s, m);
        if (tid == 0) g_partial[blockIdx.x] = s;
    }
}

// Pass B: exclusive scan of SCAN_BLOCKS partials (one small block).
__global__ void __launch_bounds__(128)
scanB_kernel() {
    __shared__ int sh[SCAN_BLOCKS];
    int tid = threadIdx.x;
    for (int i = tid; i < SCAN_BLOCKS; i += 128) sh[i] = g_partial[i];
    __syncthreads();
    if (tid == 0) {                       // 98 adds, trivially fast
        int run = 0;
        for (int i = 0; i < SCAN_BLOCKS; i++) {
            int v = sh[i]; sh[i] = run; run += v;
        }
    }
    __syncthreads();
    for (int i = tid; i < SCAN_BLOCKS; i += 128) g_pscan[i] = sh[i];
}

// Pass C: downsweep — final offsets + invdeg + cursor zeroing.
__global__ void __launch_bounds__(SCAN_CHUNK)
scanC_kernel() {
    int tid = threadIdx.x;
    int i = blockIdx.x * SCAN_CHUNK + tid;
    int v = (i < N_NODES) ? g_deg[i] : 0;
    int incl = block_incl_scan(v, tid);
    if (i < N_NODES) {
        g_off[i + 1] = g_pscan[blockIdx.x] + incl;
        g_invdeg[i]  = 1.0f / (float)(v > 1 ? v : 1);
        g_cursor[i]  = 0;
    }
    if (i == 0) g_off[0] = 0;
}

// ---------------------------------------------------------------------------
// CSR fill. Slot order within a node is atomic-arbitrary; it only permutes
// a ~32-term fp32 sum (ulp-level, far below 1e-3).
// ---------------------------------------------------------------------------
__global__ void fill_kernel(const int* __restrict__ w) {
    int e = blockIdx.x * blockDim.x + threadIdx.x;
    if (e >= N_EDGES) return;
    int is64 = g_is64;
    int s = clamp_node(load_idx(w, is64, e));
    int d = clamp_node(load_idx(w, is64, N_EDGES + e));
    int pos = atomicAdd(&g_cursor[d], 1);
    g_esrc[g_off[d] + pos] = s;
}

// ---------------------------------------------------------------------------
// Fused per-layer kernel: warp per node (see round-14 comments).
// in_sel/out_sel: 0 = kernel parameter, 1 = g_xbufA, 2 = g_xbufB.
// ---------------------------------------------------------------------------
__global__ void __launch_bounds__(TPB)
layer_kernel(const float* __restrict__ x_param, float* __restrict__ out_param,
             int in_sel, int out_sel,
             const float* __restrict__ Wl,   const float* __restrict__ bl,
             const float* __restrict__ Wr,   const float* __restrict__ Wlin,
             const float* __restrict__ blin) {
    __shared__ float sWl[D * D];
    __shared__ float sWc[D * D];
    __shared__ float sb[D];
    __shared__ float s_a[TPB / 32][D];
    __shared__ float s_x[TPB / 32][D];

    const float* x   = (in_sel == 0) ? x_param
                     : (in_sel == 1) ? (const float*)g_xbufA : (const float*)g_xbufB;
    float*       out = (out_sel == 0) ? out_param
                     : (out_sel == 1) ? (float*)g_xbufA : (float*)g_xbufB;

    int tid = threadIdx.x;
    sWl[tid] = Wl[tid];
    sWc[tid] = Wr[tid] + Wlin[tid];
    if (tid < D) sb[tid] = bl[tid] + blin[tid];
    __syncthreads();

    int wid  = tid >> 5;
    int lane = tid & 31;
    int n    = blockIdx.x * (TPB / 32) + wid;

    int start = g_off[n];
    int end   = g_off[n + 1];
    int q     = lane & 3;
    int sub   = lane >> 2;

    float4 acc = make_float4(0.f, 0.f, 0.f, 0.f);
    for (int e = start + sub; e < end; e += 8) {
        int s = g_esrc[e];
        float4 v = *reinterpret_cast<const float4*>(x + (size_t)s * D + q * 4);
        acc.x += v.x; acc.y += v.y; acc.z += v.z; acc.w += v.w;
    }
#pragma unroll
    for (int m = 4; m <= 16; m <<= 1) {
        acc.x += __shfl_xor_sync(0xffffffffu, acc.x, m);
        acc.y += __shfl_xor_sync(0xffffffffu, acc.y, m);
        acc.z += __shfl_xor_sync(0xffffffffu, acc.z, m);
        acc.w += __shfl_xor_sync(0xffffffffu, acc.w, m);
    }

    float inv = g_invdeg[n];
    if (sub == 0) {
        s_a[wid][q * 4 + 0] = acc.x * inv;
        s_a[wid][q * 4 + 1] = acc.y * inv;
        s_a[wid][q * 4 + 2] = acc.z * inv;
        s_a[wid][q * 4 + 3] = acc.w * inv;
    } else if (sub == 1) {
        float4 xv = *reinterpret_cast<const float4*>(x + (size_t)n * D + q * 4);
        s_x[wid][q * 4 + 0] = xv.x;
        s_x[wid][q * 4 + 1] = xv.y;
        s_x[wid][q * 4 + 2] = xv.z;
        s_x[wid][q * 4 + 3] = xv.w;
    }
    __syncwarp(0xffffffffu);

    if (lane < D) {
        float o = sb[lane];
        const float* wl = sWl + lane * D;
        const float* wc = sWc + lane * D;
#pragma unroll
        for (int k = 0; k < D; k++)
            o += wl[k] * s_a[wid][k] + wc[k] * s_x[wid][k];
        out[(size_t)n * D + lane] = o;
    }
}

// ---------------------------------------------------------------------------
// Launch: kernel launches ONLY.
// ---------------------------------------------------------------------------
extern "C" void kernel_launch(void* const* d_in, const int* in_sizes, int n_in,
                              void* d_out, int out_size) {
    const float* x    = (const float*)d_in[0];
    const int*   eiw  = (const int*)d_in[1];
    const float* Wl   = (const float*)d_in[2];
    const float* bl   = (const float*)d_in[3];
    const float* Wr   = (const float*)d_in[4];
    const float* Wlin = (const float*)d_in[5];
    const float* blin = (const float*)d_in[6];
    float*       out  = (float*)d_out;

    const int NODE_BLK  = (N_NODES + TPB - 1) / TPB;
    const int EDGE_BLK  = (N_EDGES + TPB - 1) / TPB;
    const int LAYER_BLK = N_NODES / (TPB / 32);      // 12500, exact

    detect_kernel<<<1, 32>>>(eiw);
    zero_kernel  <<<NODE_BLK, TPB>>>();
    deg_kernel   <<<EDGE_BLK, TPB>>>(eiw);
    scanA_kernel <<<SCAN_BLOCKS, SCAN_CHUNK>>>();
    scanB_kernel <<<1, 128>>>();
    scanC_kernel <<<SCAN_BLOCKS, SCAN_CHUNK>>>();
    fill_kernel  <<<EDGE_BLK, TPB>>>(eiw);

    layer_kernel<<<LAYER_BLK, TPB>>>(x,       nullptr, 0, 1,
        Wl + 0 * D * D, bl + 0 * D, Wr + 0 * D * D, Wlin + 0 * D * D, blin + 0 * D);
    layer_kernel<<<LAYER_BLK, TPB>>>(nullptr, nullptr, 1, 2,
        Wl + 1 * D * D, bl + 1 * D, Wr + 1 * D * D, Wlin + 1 * D * D, blin + 1 * D);
    layer_kernel<<<LAYER_BLK, TPB>>>(nullptr, out,     2, 0,
        Wl + 2 * D * D, bl + 2 * D, Wr + 2 * D * D, Wlin + 2 * D * D, blin + 2 * D);
}

// round 17
// speedup vs baseline: 1.3303x; 1.0247x over previous
#include <cuda_runtime.h>
#include <cuda_fp16.h>
#include <cstdint>

#define N_NODES 100000
#define N_EDGES 3200000
#define D 16
#define TPB 256

#define SCAN_CHUNK 1024
#define SCAN_BLOCKS ((N_NODES + SCAN_CHUNK - 1) / SCAN_CHUNK)   // 98

// -------- allocation-free scratch (__device__ globals, ~33 MB) ------------
__device__ __align__(16) float  g_xbufA[N_NODES * D];   // fp32 features (exact path)
__device__ __align__(16) float  g_xbufB[N_NODES * D];
__device__ __align__(16) __half g_xhA [N_NODES * D];    // fp16 gather mirrors
__device__ __align__(16) __half g_xhB [N_NODES * D];
__device__ float g_invdeg[N_NODES];
__device__ int   g_deg   [N_NODES];
__device__ int   g_off   [N_NODES + 1];
__device__ int   g_cursor[N_NODES];        // pre-seeded with exclusive offsets
__device__ int   g_esrc  [N_EDGES];
__device__ int   g_partial[SCAN_BLOCKS];
__device__ int   g_pscan [SCAN_BLOCKS];
__device__ int   g_is64;

__device__ __forceinline__ int clamp_node(int v) {
    v = v < 0 ? 0 : v;
    return v >= N_NODES ? N_NODES - 1 : v;
}

// ---------------------------------------------------------------------------
// Dtype detection (int32 vs int64 edge_index), one warp.
// ---------------------------------------------------------------------------
__global__ void detect_kernel(const int* __restrict__ w) {
    int lane = threadIdx.x;
    int acc = 0;
    for (int i = lane; i < 1024; i += 32) acc |= w[2 * i + 1];
#pragma unroll
    for (int m = 16; m >= 1; m >>= 1) acc |= __shfl_xor_sync(0xffffffffu, acc, m);
    if (lane == 0) g_is64 = (acc == 0) ? 1 : 0;
}

// ---------------------------------------------------------------------------
// Zero in-degree.
// ---------------------------------------------------------------------------
__global__ void zero_kernel() {
    int i = blockIdx.x * blockDim.x + threadIdx.x;
    if (i < N_NODES) g_deg[i] = 0;
}

// ---------------------------------------------------------------------------
// fp32 -> fp16 convert of the input features (gather mirror of x).
// ---------------------------------------------------------------------------
__global__ void convert_kernel(const float* __restrict__ x) {
    int i = blockIdx.x * blockDim.x + threadIdx.x;      // half2 index
    const int n2 = N_NODES * D / 2;
    if (i < n2) {
        float2 v = reinterpret_cast<const float2*>(x)[i];
        reinterpret_cast<__half2*>(g_xhA)[i] = __floats2half2_rn(v.x, v.y);
    }
}

// ---------------------------------------------------------------------------
// In-degree histogram: 2 edges per thread, streaming (evict-first) loads.
// ---------------------------------------------------------------------------
__global__ void deg_kernel(const int* __restrict__ w) {
    int t = blockIdx.x * blockDim.x + threadIdx.x;
    int e = t * 2;
    if (e >= N_EDGES) return;
    int d0, d1;
    if (g_is64) {   // dst row at element offset N_EDGES+e (int64)
        longlong2 v = __ldcs(reinterpret_cast<const longlong2*>(w) + (N_EDGES + e) / 2);
        d0 = (int)v.x; d1 = (int)v.y;
    } else {
        int2 v = __ldcs(reinterpret_cast<const int2*>(w) + (N_EDGES + e) / 2);
        d0 = v.x; d1 = v.y;
    }
    atomicAdd(&g_deg[clamp_node(d0)], 1);
    atomicAdd(&g_deg[clamp_node(d1)], 1);
}

// ---------------------------------------------------------------------------
// Grid-wide exclusive scan (3 passes).
// ---------------------------------------------------------------------------
__device__ __forceinline__ int block_incl_scan(int v, int tid) {
    __shared__ int warp_sums[32];
    int lane = tid & 31, wid = tid >> 5;
    int xs = v;
#pragma unroll
    for (int ofs = 1; ofs < 32; ofs <<= 1) {
        int y = __shfl_up_sync(0xffffffffu, xs, ofs);
        if (lane >= ofs) xs += y;
    }
    if (lane == 31) warp_sums[wid] = xs;
    __syncthreads();
    if (wid == 0) {
        int ws = warp_sums[lane];
#pragma unroll
        for (int ofs = 1; ofs < 32; ofs <<= 1) {
            int y = __shfl_up_sync(0xffffffffu, ws, ofs);
            if (lane >= ofs) ws += y;
        }
        warp_sums[lane] = ws;
    }
    __syncthreads();
    return xs + ((wid > 0) ? warp_sums[wid - 1] : 0);
}

__global__ void __launch_bounds__(SCAN_CHUNK)
scanA_kernel() {
    int tid = threadIdx.x;
    int i = blockIdx.x * SCAN_CHUNK + tid;
    int v = (i < N_NODES) ? g_deg[i] : 0;
#pragma unroll
    for (int m = 16; m >= 1; m >>= 1) v += __shfl_xor_sync(0xffffffffu, v, m);
    __shared__ int ws[32];
    if ((tid & 31) == 0) ws[tid >> 5] = v;
    __syncthreads();
    if (tid < 32) {
        int s = ws[tid];
#pragma unroll
        for (int m = 16; m >= 1; m >>= 1) s += __shfl_xor_sync(0xffffffffu, s, m);
        if (tid == 0) g_partial[blockIdx.x] = s;
    }
}

__global__ void __launch_bounds__(128)
scanB_kernel() {
    __shared__ int sh[SCAN_BLOCKS];
    int tid = threadIdx.x;
    for (int i = tid; i < SCAN_BLOCKS; i += 128) sh[i] = g_partial[i];
    __syncthreads();
    if (tid == 0) {
        int run = 0;
        for (int i = 0; i < SCAN_BLOCKS; i++) { int v = sh[i]; sh[i] = run; run += v; }
    }
    __syncthreads();
    for (int i = tid; i < SCAN_BLOCKS; i += 128) g_pscan[i] = sh[i];
}

// Downsweep: offsets, invdeg, and cursor pre-seeded with exclusive offset.
__global__ void __launch_bounds__(SCAN_CHUNK)
scanC_kernel() {
    int tid = threadIdx.x;
    int i = blockIdx.x * SCAN_CHUNK + tid;
    int v = (i < N_NODES) ? g_deg[i] : 0;
    int incl = block_incl_scan(v, tid);
    if (i < N_NODES) {
        int excl = g_pscan[blockIdx.x] + incl - v;
        g_off[i + 1] = excl + v;
        g_cursor[i]  = excl;            // fill writes directly via cursor
        g_invdeg[i]  = 1.0f / (float)(v > 1 ? v : 1);
    }
    if (i == 0) g_off[0] = 0;
}

// ---------------------------------------------------------------------------
// CSR fill: 2 edges per thread, cursor-direct (no off loads).
// ---------------------------------------------------------------------------
__global__ void fill_kernel(const int* __restrict__ w) {
    int t = blockIdx.x * blockDim.x + threadIdx.x;
    int e = t * 2;
    if (e >= N_EDGES) return;
    int s0, s1, d0, d1;
    if (g_is64) {
        longlong2 sv = __ldcs(reinterpret_cast<const longlong2*>(w) + e / 2);
        longlong2 dv = __ldcs(reinterpret_cast<const longlong2*>(w) + (N_EDGES + e) / 2);
        s0 = (int)sv.x; s1 = (int)sv.y; d0 = (int)dv.x; d1 = (int)dv.y;
    } else {
        int2 sv = __ldcs(reinterpret_cast<const int2*>(w) + e / 2);
        int2 dv = __ldcs(reinterpret_cast<const int2*>(w) + (N_EDGES + e) / 2);
        s0 = sv.x; s1 = sv.y; d0 = dv.x; d1 = dv.y;
    }
    g_esrc[atomicAdd(&g_cursor[clamp_node(d0)], 1)] = clamp_node(s0);
    g_esrc[atomicAdd(&g_cursor[clamp_node(d1)], 1)] = clamp_node(s1);
}

// ---------------------------------------------------------------------------
// Fused layer: warp per node. Gather from fp16 mirror (32B/row), accumulate
// fp32; residual path reads exact fp32 features; epilogue writes fp32 out
// and (when another layer follows) the fp16 mirror of it.
// in_sel: 0=x param, 1=g_xbufA, 2=g_xbufB (fp32 residual input)
// h_in_sel: 1=g_xhA, 2=g_xhB (fp16 gather input)
// out_sel: 0=param, 1=A, 2=B;  h_out_sel: 0=none, 1=g_xhA, 2=g_xhB
// ---------------------------------------------------------------------------
__global__ void __launch_bounds__(TPB)
layer_kernel(const float* __restrict__ x_param, float* __restrict__ out_param,
             int in_sel, int out_sel, int h_in_sel, int h_out_sel,
             const float* __restrict__ Wl,   const float* __restrict__ bl,
             const float* __restrict__ Wr,   const float* __restrict__ Wlin,
             const float* __restrict__ blin) {
    __shared__ float sWl[D * D];
    __shared__ float sWc[D * D];
    __shared__ float sb[D];
    __shared__ float s_a[TPB / 32][D];
    __shared__ float s_x[TPB / 32][D];

    const float*  x   = (in_sel == 0) ? x_param
                      : (in_sel == 1) ? (const float*)g_xbufA : (const float*)g_xbufB;
    float*        out = (out_sel == 0) ? out_param
                      : (out_sel == 1) ? (float*)g_xbufA : (float*)g_xbufB;
    const __half* xh  = (h_in_sel == 1) ? (const __half*)g_xhA : (const __half*)g_xhB;
    __half*       oh  = (h_out_sel == 1) ? (__half*)g_xhA
                      : (h_out_sel == 2) ? (__half*)g_xhB : (__half*)nullptr;

    int tid = threadIdx.x;
    sWl[tid] = Wl[tid];
    sWc[tid] = Wr[tid] + Wlin[tid];
    if (tid < D) sb[tid] = bl[tid] + blin[tid];
    __syncthreads();

    int wid  = tid >> 5;
    int lane = tid & 31;
    int n    = blockIdx.x * (TPB / 32) + wid;

    int start = g_off[n];
    int end   = g_off[n + 1];
    int q     = lane & 3;     // quad: 4 halves (8B) of the 32B fp16 row
    int sub   = lane >> 2;    // edge slot 0..7

    float4 acc = make_float4(0.f, 0.f, 0.f, 0.f);
    for (int e = start + sub; e < end; e += 8) {
        int s = g_esrc[e];
        uint2 raw = *reinterpret_cast<const uint2*>(xh + (size_t)s * D + q * 4);
        float2 f0 = __half22float2(*reinterpret_cast<const __half2*>(&raw.x));
        float2 f1 = __half22float2(*reinterpret_cast<const __half2*>(&raw.y));
        acc.x += f0.x; acc.y += f0.y; acc.z += f1.x; acc.w += f1.y;
    }
#pragma unroll
    for (int m = 4; m <= 16; m <<= 1) {
        acc.x += __shfl_xor_sync(0xffffffffu, acc.x, m);
        acc.y += __shfl_xor_sync(0xffffffffu, acc.y, m);
        acc.z += __shfl_xor_sync(0xffffffffu, acc.z, m);
        acc.w += __shfl_xor_sync(0xffffffffu, acc.w, m);
    }

    float inv = g_invdeg[n];
    if (sub == 0) {
        s_a[wid][q * 4 + 0] = acc.x * inv;
        s_a[wid][q * 4 + 1] = acc.y * inv;
        s_a[wid][q * 4 + 2] = acc.z * inv;
        s_a[wid][q * 4 + 3] = acc.w * inv;
    } else if (sub == 1) {
        float4 xv = *reinterpret_cast<const float4*>(x + (size_t)n * D + q * 4);
        s_x[wid][q * 4 + 0] = xv.x;
        s_x[wid][q * 4 + 1] = xv.y;
        s_x[wid][q * 4 + 2] = xv.z;
        s_x[wid][q * 4 + 3] = xv.w;
    }
    __syncwarp(0xffffffffu);

    if (lane < D) {
        float o = sb[lane];
        const float* wl = sWl + lane * D;
        const float* wc = sWc + lane * D;
#pragma unroll
        for (int k = 0; k < D; k++)
            o += wl[k] * s_a[wid][k] + wc[k] * s_x[wid][k];
        out[(size_t)n * D + lane] = o;
        if (oh) oh[(size_t)n * D + lane] = __float2half_rn(o);
    }
}

// ---------------------------------------------------------------------------
// Launch: kernel launches ONLY.
// ---------------------------------------------------------------------------
extern "C" void kernel_launch(void* const* d_in, const int* in_sizes, int n_in,
                              void* d_out, int out_size) {
    const float* x    = (const float*)d_in[0];
    const int*   eiw  = (const int*)d_in[1];
    const float* Wl   = (const float*)d_in[2];
    const float* bl   = (const float*)d_in[3];
    const float* Wr   = (const float*)d_in[4];
    const float* Wlin = (const float*)d_in[5];
    const float* blin = (const float*)d_in[6];
    float*       out  = (float*)d_out;

    const int NODE_BLK  = (N_NODES + TPB - 1) / TPB;
    const int EDGE2_BLK = (N_EDGES / 2 + TPB - 1) / TPB;
    const int CONV_BLK  = (N_NODES * D / 2 + TPB - 1) / TPB;
    const int LAYER_BLK = N_NODES / (TPB / 32);      // 12500, exact

    detect_kernel <<<1, 32>>>(eiw);
    zero_kernel   <<<NODE_BLK, TPB>>>();
    convert_kernel<<<CONV_BLK, TPB>>>(x);            // x -> g_xhA
    deg_kernel    <<<EDGE2_BLK, TPB>>>(eiw);
    scanA_kernel  <<<SCAN_BLOCKS, SCAN_CHUNK>>>();
    scanB_kernel  <<<1, 128>>>();
    scanC_kernel  <<<SCAN_BLOCKS, SCAN_CHUNK>>>();
    fill_kernel   <<<EDGE2_BLK, TPB>>>(eiw);

    // L0: fp32 x -> A,  fp16 hA -> hB
    layer_kernel<<<LAYER_BLK, TPB>>>(x,       nullptr, 0, 1, 1, 2,
        Wl + 0 * D * D, bl + 0 * D, Wr + 0 * D * D, Wlin + 0 * D * D, blin + 0 * D);
    // L1: A -> B,  hB -> hA
    layer_kernel<<<LAYER_BLK, TPB>>>(nullptr, nullptr, 1, 2, 2, 1,
        Wl + 1 * D * D, bl + 1 * D, Wr + 1 * D * D, Wlin + 1 * D * D, blin + 1 * D);
    // L2: B -> out, hA -> (none)
    layer_kernel<<<LAYER_BLK, TPB>>>(nullptr, out,     2, 0, 1, 0,
        Wl + 2 * D * D, bl + 2 * D, Wr + 2 * D * D, Wlin + 2 * D * D, blin + 2 * D);
}